// round 11
// baseline (speedup 1.0000x reference)
#include <cuda_runtime.h>
#include <cuda_fp16.h>
#include <cstdint>

// BlockSparse: out = x @ (mask*W)^T + bias.  M=8192, N=4096, K=4096 fp32.
// Mask: 256-blocks, keep (i,j) iff (i+j)%16 >= 8 -> K_eff = 2048 per column block.
//
// R11: fp16 m16n8k16 single pass, 8 warps of 64x64.  BK=128 chunks with a
// 2-stage 96KB double buffer -> 16 chunk boundaries instead of 32 (boundary
// overhead measured ~660cyc each in R10).  cp.async for chunk c+1 spread
// 4/kstep over ksteps 0-5 (commit at 5); single barrier per chunk at kstep 7
// (covers cp.async visibility for stage c+1 AND WAR hazard on stage c).

#define M_DIM 8192
#define N_DIM 4096
#define K_DIM 4096

#define BM 128
#define BN 256
#define BK 128
#define NCHUNKS 16                         // 8 surviving 256-blocks * 2
#define A_PART (128 * 256)                 // 128 rows x 128 fp16 (256B) = 32 KB
#define B_PART (256 * 256)                 // 64 KB
#define OFF_A 0
#define OFF_B (A_PART)
#define STAGE_BYTES (A_PART + B_PART)      // 96 KB
#define SMEM_DYN (2 * STAGE_BYTES + 2048)  // 194 KB

__device__ __half g_x[(size_t)M_DIM * K_DIM];
__device__ __half g_w[(size_t)N_DIM * K_DIM];

// ---------- helpers ----------
__device__ __forceinline__ uint32_t smem_u32(const void* p) {
    uint32_t a;
    asm("{ .reg .u64 t; cvta.to.shared.u64 t, %1; cvt.u32.u64 %0, t; }" : "=r"(a) : "l"(p));
    return a;
}
__device__ __forceinline__ void cp16(uint32_t dst, const void* src) {
    asm volatile("cp.async.cg.shared.global [%0], [%1], 16;" :: "r"(dst), "l"(src));
}
__device__ __forceinline__ void cp_commit() { asm volatile("cp.async.commit_group;" ::: "memory"); }
template <int N> __device__ __forceinline__ void cp_wait() {
    asm volatile("cp.async.wait_group %0;" :: "n"(N) : "memory");
}
__device__ __forceinline__ void ldsm_x4(uint32_t* r, uint32_t addr) {
    asm volatile("ldmatrix.sync.aligned.m8n8.x4.shared.b16 {%0,%1,%2,%3}, [%4];"
                 : "=r"(r[0]), "=r"(r[1]), "=r"(r[2]), "=r"(r[3]) : "r"(addr));
}
__device__ __forceinline__ void mma_f16(float* c, const uint32_t* a, const uint32_t* b) {
    asm volatile(
        "mma.sync.aligned.m16n8k16.row.col.f32.f16.f16.f32 "
        "{%0,%1,%2,%3}, {%4,%5,%6,%7}, {%8,%9}, {%0,%1,%2,%3};"
        : "+f"(c[0]), "+f"(c[1]), "+f"(c[2]), "+f"(c[3])
        : "r"(a[0]), "r"(a[1]), "r"(a[2]), "r"(a[3]), "r"(b[0]), "r"(b[1]));
}
// 256B rows = 16 x 16B chunks; physical chunk = c ^ (r & 7)
__device__ __forceinline__ uint32_t swz(int r, int c) {
    return (uint32_t)(r * 256 + ((c ^ (r & 7)) << 4));
}

// ---------- prepass: fp32 -> fp16; W converts only unmasked blocks ----------
__global__ __launch_bounds__(256) void cvt_kernel(const float* __restrict__ x,
                                                  const float* __restrict__ w) {
    const long NX = (long)M_DIM * K_DIM / 4;
    const long NW = (long)N_DIM * 8 * 64;
    const long NT = NX + NW;
    long stride = (long)gridDim.x * blockDim.x;
    for (long t = (long)blockIdx.x * blockDim.x + threadIdx.x; t < NT; t += stride) {
        long o;
        const float* src;
        if (t < NX) {
            o = t;
            src = x;
        } else {
            const long u = t - NX;
            const int row = (int)(u >> 9);
            const int rem = (int)(u & 511);
            const int kb = rem >> 6;
            const int f4 = rem & 63;
            const int i = row >> 8;
            const int j = (8 + kb - (i & 15)) & 15;
            o = (long)row * (K_DIM / 4) + j * 64 + f4;
            src = w;
        }
        float4 v = reinterpret_cast<const float4*>(src)[o];
        __half2 h0 = __floats2half2_rn(v.x, v.y);
        __half2 h1 = __floats2half2_rn(v.z, v.w);
        uint2 pk = make_uint2(*reinterpret_cast<uint32_t*>(&h0),
                              *reinterpret_cast<uint32_t*>(&h1));
        reinterpret_cast<uint2*>(t < NX ? g_x : g_w)[o] = pk;
    }
}

// ---------- main GEMM ----------
__global__ __launch_bounds__(256, 1)
void bs_f16_kernel(const float* __restrict__ bias, float* __restrict__ out) {
    extern __shared__ char smem[];
    const uint32_t sbase = smem_u32(smem);
    float* sbias = reinterpret_cast<float*>(smem + 2 * STAGE_BYTES);

    const int tid = threadIdx.x;
    const int wid = tid >> 5;
    const int lane = tid & 31;
    const int nBase = blockIdx.x * BN;
    const int mBase = blockIdx.y * BM;
    const int wm = wid & 1;      // 0..1 over M (64 rows)
    const int wn = wid >> 1;     // 0..3 over N (64 cols)

    int ks[8];
    {
        int n = 0;
        const int i = blockIdx.x;
#pragma unroll
        for (int j = 0; j < 16; j++)
            if (((i + j) & 15) >= 8) ks[n++] = j * 256;
    }

    if (tid < 64) {
        *reinterpret_cast<float4*>(&sbias[tid * 4]) =
            *reinterpret_cast<const float4*>(&bias[nBase + tid * 4]);
    }

    // one 16B piece (ii of 24) for a chunk with k-origin lk0 into stage st
    auto cp_piece = [&](int lk0, uint32_t st, int ii) {
        const int idx = tid + ii * 256;           // 0..6143
        uint32_t dst;
        const __half* src;
        if (idx < 2048) {                         // A: 128 rows x 16 chunks
            const int r = idx >> 4, cc = idx & 15;
            src = g_x + ((size_t)(mBase + r) * K_DIM + lk0 + cc * 8);
            dst = st + OFF_A + swz(r, cc);
        } else {                                  // B: 256 rows x 16 chunks
            const int t = idx - 2048;
            const int r = t >> 4, cc = t & 15;
            src = g_w + ((size_t)(nBase + r) * K_DIM + lk0 + cc * 8);
            dst = st + OFF_B + swz(r, cc);
        }
        cp16(dst, src);
    };

    // fragment addressing (row bases multiples of 8 -> row&7 == lane&7)
    const int q = lane >> 3;
    const int l7 = lane & 7;
    const int qa = q >> 1;           // A k-half select
    const int qb = q & 1;            // B k-half select
    const uint32_t aOff0 = OFF_A + (uint32_t)(wm * 64 + ((q & 1) << 3) + l7) * 256;
    const uint32_t bOff0 = OFF_B + (uint32_t)(wn * 64 + ((q >> 1) << 3) + l7) * 256;

    auto ldA = [&](uint32_t stb, int kk, uint32_t (*dst)[4]) {
        const uint32_t t = (uint32_t)(((2 * kk + qa) ^ l7) << 4);
#pragma unroll
        for (int mi = 0; mi < 4; mi++)
            ldsm_x4(dst[mi], stb + aOff0 + (uint32_t)(mi * 16 * 256) + t);
    };
    auto ldB = [&](uint32_t stb, int kk, uint32_t* dst) {
        const uint32_t t = (uint32_t)(((2 * kk + qb) ^ l7) << 4);
#pragma unroll
        for (int nip = 0; nip < 4; nip++)
            ldsm_x4(dst + nip * 4, stb + bOff0 + (uint32_t)(nip * 16 * 256) + t);
    };

    float acc[4][8][4];
#pragma unroll
    for (int a = 0; a < 4; a++)
#pragma unroll
        for (int b = 0; b < 8; b++)
#pragma unroll
            for (int p = 0; p < 4; p++) acc[a][b][p] = 0.0f;

    uint32_t af[2][4][4];
    uint32_t bf[2][16];

    // prologue: fully load chunk 0 into stage 0
    {
        const int k0 = ks[0];
#pragma unroll
        for (int ii = 0; ii < 24; ii++) cp_piece(k0, sbase, ii);
        cp_commit();
        cp_wait<0>();
        __syncthreads();
        ldA(sbase, 0, af[0]);
        ldB(sbase, 0, bf[0]);
    }

#pragma unroll 1
    for (int c = 0; c < NCHUNKS; c++) {
        const uint32_t st  = sbase + (uint32_t)(c & 1) * STAGE_BYTES;
        const uint32_t stn = sbase + (uint32_t)((c + 1) & 1) * STAGE_BYTES;
        const bool doLoad = (c + 1 < NCHUNKS);
        const int nc = doLoad ? c + 1 : 0;
        const int lk0 = ks[nc >> 1] + (nc & 1) * BK;

#pragma unroll
        for (int kstep = 0; kstep < 8; kstep++) {
            const int cur = kstep & 1, nxt = cur ^ 1;
            if (kstep < 7) {
                // prefetch next kstep's fragments from current stage
                ldA(st, kstep + 1, af[nxt]);
                ldB(st, kstep + 1, bf[nxt]);
                // 4 of 24 cp.async pieces for chunk c+1 (ksteps 0..5)
                if (doLoad && kstep < 6) {
#pragma unroll
                    for (int ii = 0; ii < 4; ii++) cp_piece(lk0, stn, kstep * 4 + ii);
                    if (kstep == 5) cp_commit();
                }
            } else {
                // chunk boundary: drain own cp.asyncs, publish via barrier,
                // then prefetch next chunk's kstep-0 fragments.
                cp_wait<0>();
                __syncthreads();
                if (doLoad) {
                    ldA(stn, 0, af[nxt]);
                    ldB(stn, 0, bf[nxt]);
                }
            }
            // 32 MMAs on current fragments
#pragma unroll
            for (int nip = 0; nip < 4; nip++)
#pragma unroll
                for (int half = 0; half < 2; half++) {
                    const int ni = nip * 2 + half;
#pragma unroll
                    for (int mi = 0; mi < 4; mi++)
                        mma_f16(acc[mi][ni], af[cur][mi], &bf[cur][nip * 4 + half * 2]);
                }
        }
    }

    // epilogue: + bias
    const int qid = lane >> 2;
    const int qn = (lane & 3) * 2;
#pragma unroll
    for (int mi = 0; mi < 4; mi++) {
        const int m0 = mBase + wm * 64 + mi * 16 + qid;
#pragma unroll
        for (int ni = 0; ni < 8; ni++) {
            const int ncol = wn * 64 + ni * 8 + qn;
            const float b0 = sbias[ncol], b1 = sbias[ncol + 1];
            float2 o0 = make_float2(acc[mi][ni][0] + b0, acc[mi][ni][1] + b1);
            float2 o1 = make_float2(acc[mi][ni][2] + b0, acc[mi][ni][3] + b1);
            *reinterpret_cast<float2*>(&out[(size_t)m0 * N_DIM + nBase + ncol]) = o0;
            *reinterpret_cast<float2*>(&out[(size_t)(m0 + 8) * N_DIM + nBase + ncol]) = o1;
        }
    }
}

// ---------- launch ----------
extern "C" void kernel_launch(void* const* d_in, const int* in_sizes, int n_in,
                              void* d_out, int out_size) {
    const float* x    = (const float*)d_in[0];
    const float* w    = (const float*)d_in[1];
    const float* bias = (const float*)d_in[2];
    float* out = (float*)d_out;

    cvt_kernel<<<6144, 256>>>(x, w);

    cudaFuncSetAttribute(bs_f16_kernel, cudaFuncAttributeMaxDynamicSharedMemorySize, SMEM_DYN);
    dim3 grid(N_DIM / BN, M_DIM / BM);   // 16 x 64
    bs_f16_kernel<<<grid, 256, SMEM_DYN>>>(bias, out);
}

// round 12
// speedup vs baseline: 1.0534x; 1.0534x over previous
#include <cuda_runtime.h>
#include <cuda_fp16.h>
#include <cstdint>

// BlockSparse: out = x @ (mask*W)^T + bias.  M=8192, N=4096, K=4096 fp32.
// Mask: 256-blocks, keep (i,j) iff (i+j)%16 >= 8 -> K_eff = 2048 per column block.
//
// R12: fp16 m16n8k16 single pass, warp tile 64x64.  CTA shrunk to 128x128 with
// 4 warps and 3-stage 32KB buffering -> 2 CTAs/SM.  The two CTAs' chunk
// boundaries interleave, so the tensor pipe keeps issuing while one CTA waits
// at its barrier (the ~660cyc/chunk boundary cost measured in R10/R11).

#define M_DIM 8192
#define N_DIM 4096
#define K_DIM 4096

#define BM 128
#define BN 128
#define BK 64
#define NCHUNKS 32                         // 8 surviving 256-blocks * 4
#define STAGES 3
#define A_PART (128 * 128)                 // 128 rows x 64 fp16 (128B) = 16 KB
#define B_PART (128 * 128)                 // 16 KB
#define OFF_A 0
#define OFF_B (A_PART)
#define STAGE_BYTES (A_PART + B_PART)      // 32 KB
#define SMEM_DYN (STAGES * STAGE_BYTES + 1024)

__device__ __half g_x[(size_t)M_DIM * K_DIM];
__device__ __half g_w[(size_t)N_DIM * K_DIM];

// ---------- helpers ----------
__device__ __forceinline__ uint32_t smem_u32(const void* p) {
    uint32_t a;
    asm("{ .reg .u64 t; cvta.to.shared.u64 t, %1; cvt.u32.u64 %0, t; }" : "=r"(a) : "l"(p));
    return a;
}
__device__ __forceinline__ void cp16(uint32_t dst, const void* src) {
    asm volatile("cp.async.cg.shared.global [%0], [%1], 16;" :: "r"(dst), "l"(src));
}
__device__ __forceinline__ void cp_commit() { asm volatile("cp.async.commit_group;" ::: "memory"); }
template <int N> __device__ __forceinline__ void cp_wait() {
    asm volatile("cp.async.wait_group %0;" :: "n"(N) : "memory");
}
__device__ __forceinline__ void ldsm_x4(uint32_t* r, uint32_t addr) {
    asm volatile("ldmatrix.sync.aligned.m8n8.x4.shared.b16 {%0,%1,%2,%3}, [%4];"
                 : "=r"(r[0]), "=r"(r[1]), "=r"(r[2]), "=r"(r[3]) : "r"(addr));
}
__device__ __forceinline__ void mma_f16(float* c, const uint32_t* a, const uint32_t* b) {
    asm volatile(
        "mma.sync.aligned.m16n8k16.row.col.f32.f16.f16.f32 "
        "{%0,%1,%2,%3}, {%4,%5,%6,%7}, {%8,%9}, {%0,%1,%2,%3};"
        : "+f"(c[0]), "+f"(c[1]), "+f"(c[2]), "+f"(c[3])
        : "r"(a[0]), "r"(a[1]), "r"(a[2]), "r"(a[3]), "r"(b[0]), "r"(b[1]));
}
// 128B rows = 8 x 16B chunks; physical chunk = c ^ (r & 7)
__device__ __forceinline__ uint32_t swz(int r, int c) {
    return (uint32_t)(r * 128 + ((c ^ (r & 7)) << 4));
}

// ---------- prepass: fp32 -> fp16; W converts only unmasked blocks ----------
__global__ __launch_bounds__(256) void cvt_kernel(const float* __restrict__ x,
                                                  const float* __restrict__ w) {
    const long NX = (long)M_DIM * K_DIM / 4;
    const long NW = (long)N_DIM * 8 * 64;
    const long NT = NX + NW;
    long stride = (long)gridDim.x * blockDim.x;
    for (long t = (long)blockIdx.x * blockDim.x + threadIdx.x; t < NT; t += stride) {
        long o;
        const float* src;
        if (t < NX) {
            o = t;
            src = x;
        } else {
            const long u = t - NX;
            const int row = (int)(u >> 9);
            const int rem = (int)(u & 511);
            const int kb = rem >> 6;
            const int f4 = rem & 63;
            const int i = row >> 8;
            const int j = (8 + kb - (i & 15)) & 15;
            o = (long)row * (K_DIM / 4) + j * 64 + f4;
            src = w;
        }
        float4 v = reinterpret_cast<const float4*>(src)[o];
        __half2 h0 = __floats2half2_rn(v.x, v.y);
        __half2 h1 = __floats2half2_rn(v.z, v.w);
        uint2 pk = make_uint2(*reinterpret_cast<uint32_t*>(&h0),
                              *reinterpret_cast<uint32_t*>(&h1));
        reinterpret_cast<uint2*>(t < NX ? g_x : g_w)[o] = pk;
    }
}

// ---------- main GEMM ----------
__global__ __launch_bounds__(128, 2)
void bs_f16_kernel(const float* __restrict__ bias, float* __restrict__ out) {
    extern __shared__ char smem[];
    const uint32_t sbase = smem_u32(smem);
    float* sbias = reinterpret_cast<float*>(smem + STAGES * STAGE_BYTES);

    const int tid = threadIdx.x;
    const int wid = tid >> 5;
    const int lane = tid & 31;
    const int nBase = blockIdx.x * BN;
    const int mBase = blockIdx.y * BM;
    const int wm = wid & 1;      // 0..1 over M (64 rows)
    const int wn = wid >> 1;     // 0..1 over N (64 cols)

    int ks[8];
    {
        int n = 0;
        const int i = blockIdx.x >> 1;       // 256-col block index (BN==128)
#pragma unroll
        for (int j = 0; j < 16; j++)
            if (((i + j) & 15) >= 8) ks[n++] = j * 256;
    }

    if (tid < 32) {
        *reinterpret_cast<float4*>(&sbias[tid * 4]) =
            *reinterpret_cast<const float4*>(&bias[nBase + tid * 4]);
    }

    // one 16B piece (ii of 16) for chunk with k-origin lk0 into stage st
    auto cp_piece = [&](int lk0, uint32_t st, int ii) {
        const int idx = tid + ii * 128;       // 0..2047
        uint32_t dst;
        const __half* src;
        if (idx < 1024) {                     // A: 128 rows x 8 chunks
            const int r = idx >> 3, cc = idx & 7;
            src = g_x + ((size_t)(mBase + r) * K_DIM + lk0 + cc * 8);
            dst = st + OFF_A + swz(r, cc);
        } else {                              // B: 128 rows x 8 chunks
            const int t = idx - 1024;
            const int r = t >> 3, cc = t & 7;
            src = g_w + ((size_t)(nBase + r) * K_DIM + lk0 + cc * 8);
            dst = st + OFF_B + swz(r, cc);
        }
        cp16(dst, src);
    };

    auto load_chunk_all = [&](int c) {
        const int k0 = ks[c >> 2] + (c & 3) * BK;
        const uint32_t st = sbase + (uint32_t)(c % STAGES) * STAGE_BYTES;
#pragma unroll
        for (int ii = 0; ii < 16; ii++) cp_piece(k0, st, ii);
        cp_commit();
    };

    // fragment addressing (row bases multiples of 8 -> row&7 == lane&7)
    const int q = lane >> 3;
    const int l7 = lane & 7;
    const int qa = q >> 1;
    const int qb = q & 1;
    const uint32_t aOff0 = OFF_A + (uint32_t)(wm * 64 + ((q & 1) << 3) + l7) * 128;
    const uint32_t bOff0 = OFF_B + (uint32_t)(wn * 64 + ((q >> 1) << 3) + l7) * 128;

    auto ldA = [&](uint32_t stb, int kk, uint32_t (*dst)[4]) {
        const uint32_t t = (uint32_t)(((2 * kk + qa) ^ l7) << 4);
#pragma unroll
        for (int mi = 0; mi < 4; mi++)
            ldsm_x4(dst[mi], stb + aOff0 + (uint32_t)(mi * 16 * 128) + t);
    };
    auto ldB = [&](uint32_t stb, int kk, uint32_t* dst) {
        const uint32_t t = (uint32_t)(((2 * kk + qb) ^ l7) << 4);
#pragma unroll
        for (int nip = 0; nip < 4; nip++)
            ldsm_x4(dst + nip * 4, stb + bOff0 + (uint32_t)(nip * 16 * 128) + t);
    };

    float acc[4][8][4];
#pragma unroll
    for (int a = 0; a < 4; a++)
#pragma unroll
        for (int b = 0; b < 8; b++)
#pragma unroll
            for (int p = 0; p < 4; p++) acc[a][b][p] = 0.0f;

    uint32_t af[2][4][4];
    uint32_t bf[2][16];

    // prologue: load chunks 0 and 1
    load_chunk_all(0);
    load_chunk_all(1);
    cp_wait<1>();
    __syncthreads();
    ldA(sbase, 0, af[0]);
    ldB(sbase, 0, bf[0]);

#pragma unroll 1
    for (int c = 0; c < NCHUNKS; c++) {
        const uint32_t st  = sbase + (uint32_t)(c % STAGES) * STAGE_BYTES;
        const uint32_t stn = sbase + (uint32_t)((c + 1) % STAGES) * STAGE_BYTES;
        const bool doLoad = (c + 2 < NCHUNKS);
        const int nc = doLoad ? c + 2 : 0;
        const int lk0 = ks[nc >> 2] + (nc & 3) * BK;
        const uint32_t lst = sbase + (uint32_t)(nc % STAGES) * STAGE_BYTES;

#pragma unroll
        for (int kstep = 0; kstep < 4; kstep++) {
            const int cur = kstep & 1, nxt = cur ^ 1;
            // prefetch next fragments (next kstep, or next chunk's kstep 0)
            if (kstep < 3) {
                ldA(st, kstep + 1, af[nxt]);
                ldB(st, kstep + 1, bf[nxt]);
            } else if (c + 1 < NCHUNKS) {
                ldA(stn, 0, af[nxt]);
                ldB(stn, 0, bf[nxt]);
            }
            // 8 of 16 cp.async pieces for chunk c+2 in ksteps 0-1 (early commit)
            if (doLoad && kstep < 2) {
#pragma unroll
                for (int ii = 0; ii < 8; ii++) cp_piece(lk0, lst, kstep * 8 + ii);
                if (kstep == 1) cp_commit();
            }
            // 32 MMAs
#pragma unroll
            for (int nip = 0; nip < 4; nip++)
#pragma unroll
                for (int half = 0; half < 2; half++) {
                    const int ni = nip * 2 + half;
#pragma unroll
                    for (int mi = 0; mi < 4; mi++)
                        mma_f16(acc[mi][ni], af[cur][mi], &bf[cur][nip * 4 + half * 2]);
                }
        }
        // chunk boundary: ensure stage c+1 complete and published; WAR on the
        // stage c+2 writes covered by the same barrier.
        if (c + 1 < NCHUNKS) {
            cp_wait<1>();
            __syncthreads();
        }
    }

    // epilogue: + bias
    const int qid = lane >> 2;
    const int qn = (lane & 3) * 2;
#pragma unroll
    for (int mi = 0; mi < 4; mi++) {
        const int m0 = mBase + wm * 64 + mi * 16 + qid;
#pragma unroll
        for (int ni = 0; ni < 8; ni++) {
            const int ncol = wn * 64 + ni * 8 + qn;
            const float b0 = sbias[ncol], b1 = sbias[ncol + 1];
            float2 o0 = make_float2(acc[mi][ni][0] + b0, acc[mi][ni][1] + b1);
            float2 o1 = make_float2(acc[mi][ni][2] + b0, acc[mi][ni][3] + b1);
            *reinterpret_cast<float2*>(&out[(size_t)m0 * N_DIM + nBase + ncol]) = o0;
            *reinterpret_cast<float2*>(&out[(size_t)(m0 + 8) * N_DIM + nBase + ncol]) = o1;
        }
    }
}

// ---------- launch ----------
extern "C" void kernel_launch(void* const* d_in, const int* in_sizes, int n_in,
                              void* d_out, int out_size) {
    const float* x    = (const float*)d_in[0];
    const float* w    = (const float*)d_in[1];
    const float* bias = (const float*)d_in[2];
    float* out = (float*)d_out;

    cvt_kernel<<<6144, 256>>>(x, w);

    cudaFuncSetAttribute(bs_f16_kernel, cudaFuncAttributeMaxDynamicSharedMemorySize, SMEM_DYN);
    dim3 grid(N_DIM / BN, M_DIM / BM);   // 32 x 64
    bs_f16_kernel<<<grid, 128, SMEM_DYN>>>(bias, out);
}

// round 13
// speedup vs baseline: 1.0545x; 1.0010x over previous
#include <cuda_runtime.h>
#include <cuda_fp16.h>
#include <cstdint>

// BlockSparse: out = x @ (mask*W)^T + bias.  M=8192, N=4096, K=4096 fp32.
// Mask: 256-blocks, keep (i,j) iff (i+j)%16 >= 8 -> K_eff = 2048 per column block.
//
// R13: fp16 m16n8k16 single pass, warp tile 64x64, CTA 128x128 (4 warps),
// 3-stage cp.async, 2 CTAs/SM.  PERSISTENT: 304 CTAs each consume a continuous
// chunk stream across ~7 tiles (the stage ring never drains; next tile's loads
// overlap the epilogue).  Boundary reordered: cp_wait<1>+bar BEFORE the
// cross-chunk fragment prefetch (fixes R12's latent race).

#define M_DIM 8192
#define N_DIM 4096
#define K_DIM 4096

#define BM 128
#define BN 128
#define BK 64
#define NTILES 2048                        // 64 m-tiles x 32 n-tiles
#define GRID_P 304                         // 2 CTAs/SM x 152 SMs
#define STAGES 3
#define A_PART (128 * 128)                 // 16 KB
#define B_PART (128 * 128)                 // 16 KB
#define OFF_A 0
#define OFF_B (A_PART)
#define STAGE_BYTES (A_PART + B_PART)      // 32 KB
#define SMEM_DYN (STAGES * STAGE_BYTES + 256)

__device__ __half g_x[(size_t)M_DIM * K_DIM];
__device__ __half g_w[(size_t)N_DIM * K_DIM];

// ---------- helpers ----------
__device__ __forceinline__ uint32_t smem_u32(const void* p) {
    uint32_t a;
    asm("{ .reg .u64 t; cvta.to.shared.u64 t, %1; cvt.u32.u64 %0, t; }" : "=r"(a) : "l"(p));
    return a;
}
__device__ __forceinline__ void cp16(uint32_t dst, const void* src) {
    asm volatile("cp.async.cg.shared.global [%0], [%1], 16;" :: "r"(dst), "l"(src));
}
__device__ __forceinline__ void cp_commit() { asm volatile("cp.async.commit_group;" ::: "memory"); }
template <int N> __device__ __forceinline__ void cp_wait() {
    asm volatile("cp.async.wait_group %0;" :: "n"(N) : "memory");
}
__device__ __forceinline__ void ldsm_x4(uint32_t* r, uint32_t addr) {
    asm volatile("ldmatrix.sync.aligned.m8n8.x4.shared.b16 {%0,%1,%2,%3}, [%4];"
                 : "=r"(r[0]), "=r"(r[1]), "=r"(r[2]), "=r"(r[3]) : "r"(addr));
}
__device__ __forceinline__ void mma_f16(float* c, const uint32_t* a, const uint32_t* b) {
    asm volatile(
        "mma.sync.aligned.m16n8k16.row.col.f32.f16.f16.f32 "
        "{%0,%1,%2,%3}, {%4,%5,%6,%7}, {%8,%9}, {%0,%1,%2,%3};"
        : "+f"(c[0]), "+f"(c[1]), "+f"(c[2]), "+f"(c[3])
        : "r"(a[0]), "r"(a[1]), "r"(a[2]), "r"(a[3]), "r"(b[0]), "r"(b[1]));
}
__device__ __forceinline__ uint32_t swz(int r, int c) {
    return (uint32_t)(r * 128 + ((c ^ (r & 7)) << 4));
}

// ---------- prepass: fp32 -> fp16; W converts only unmasked blocks ----------
__global__ __launch_bounds__(256) void cvt_kernel(const float* __restrict__ x,
                                                  const float* __restrict__ w) {
    const long NX = (long)M_DIM * K_DIM / 4;
    const long NW = (long)N_DIM * 8 * 64;
    const long NT = NX + NW;
    long stride = (long)gridDim.x * blockDim.x;
    for (long t = (long)blockIdx.x * blockDim.x + threadIdx.x; t < NT; t += stride) {
        long o;
        const float* src;
        if (t < NX) {
            o = t;
            src = x;
        } else {
            const long u = t - NX;
            const int row = (int)(u >> 9);
            const int rem = (int)(u & 511);
            const int kb = rem >> 6;
            const int f4 = rem & 63;
            const int i = row >> 8;
            const int j = (8 + kb - (i & 15)) & 15;
            o = (long)row * (K_DIM / 4) + j * 64 + f4;
            src = w;
        }
        float4 v = reinterpret_cast<const float4*>(src)[o];
        __half2 h0 = __floats2half2_rn(v.x, v.y);
        __half2 h1 = __floats2half2_rn(v.z, v.w);
        uint2 pk = make_uint2(*reinterpret_cast<uint32_t*>(&h0),
                              *reinterpret_cast<uint32_t*>(&h1));
        reinterpret_cast<uint2*>(t < NX ? g_x : g_w)[o] = pk;
    }
}

// ---------- main GEMM (persistent) ----------
__global__ __launch_bounds__(128, 2)
void bs_f16_kernel(const float* __restrict__ bias, float* __restrict__ out) {
    extern __shared__ char smem[];
    const uint32_t sbase = smem_u32(smem);

    const int tid = threadIdx.x;
    const int wid = tid >> 5;
    const int lane = tid & 31;
    const int wm = wid & 1;      // 0..1 over M (64 rows)
    const int wn = wid >> 1;     // 0..1 over N (64 cols)
    const int t0 = blockIdx.x;

    // number of tiles for this CTA
    int nT = 0;
    for (int t = t0; t < NTILES; t += GRID_P) nT++;
    const int gcEnd = nT * 32;
    if (gcEnd == 0) return;

    // tile j (local) -> bases; tile index tt = t0 + GRID_P*j; n = tt&31, m = tt>>5
    auto tileMB = [&](int j) { return ((t0 + GRID_P * j) >> 5) * BM; };
    auto tileNB = [&](int j) { return ((t0 + GRID_P * j) & 31) * BN; };
    // chunk cc (0..31) of a tile with column-block i -> k origin
    auto chunkK0 = [&](int i, int cc) {
        const int kb = cc >> 2;
        const int j = (8 + kb - (i & 15)) & 15;
        return j * 256 + (cc & 3) * BK;
    };

    // one 16B piece (ii of 16) into stage st
    auto cp_piece = [&](int lmB, int lnB, int lk0, uint32_t st, int ii) {
        const int idx = tid + ii * 128;       // 0..2047
        uint32_t dst;
        const __half* src;
        if (idx < 1024) {                     // A
            const int r = idx >> 3, cc = idx & 7;
            src = g_x + ((size_t)(lmB + r) * K_DIM + lk0 + cc * 8);
            dst = st + OFF_A + swz(r, cc);
        } else {                              // B
            const int t = idx - 1024;
            const int r = t >> 3, cc = t & 7;
            src = g_w + ((size_t)(lnB + r) * K_DIM + lk0 + cc * 8);
            dst = st + OFF_B + swz(r, cc);
        }
        cp16(dst, src);
    };

    // fragment addressing
    const int q = lane >> 3;
    const int l7 = lane & 7;
    const int qa = q >> 1;
    const int qb = q & 1;
    const uint32_t aOff0 = OFF_A + (uint32_t)(wm * 64 + ((q & 1) << 3) + l7) * 128;
    const uint32_t bOff0 = OFF_B + (uint32_t)(wn * 64 + ((q >> 1) << 3) + l7) * 128;

    auto ldA = [&](uint32_t stb, int kk, uint32_t (*dst)[4]) {
        const uint32_t t = (uint32_t)(((2 * kk + qa) ^ l7) << 4);
#pragma unroll
        for (int mi = 0; mi < 4; mi++)
            ldsm_x4(dst[mi], stb + aOff0 + (uint32_t)(mi * 16 * 128) + t);
    };
    auto ldB = [&](uint32_t stb, int kk, uint32_t* dst) {
        const uint32_t t = (uint32_t)(((2 * kk + qb) ^ l7) << 4);
#pragma unroll
        for (int nip = 0; nip < 4; nip++)
            ldsm_x4(dst + nip * 4, stb + bOff0 + (uint32_t)(nip * 16 * 128) + t);
    };

    float acc[4][8][4];
#pragma unroll
    for (int a = 0; a < 4; a++)
#pragma unroll
        for (int b = 0; b < 8; b++)
#pragma unroll
            for (int p = 0; p < 4; p++) acc[a][b][p] = 0.0f;

    uint32_t af[2][4][4];
    uint32_t bf[2][16];

    // prologue: chunks 0 and 1 of tile 0
    {
        const int mB = tileMB(0), nB = tileNB(0), i = (tileNB(0) / BN) >> 1;
#pragma unroll
        for (int ii = 0; ii < 16; ii++) cp_piece(mB, nB, chunkK0(i, 0), sbase, ii);
        cp_commit();
        const uint32_t s1 = sbase + STAGE_BYTES;
#pragma unroll
        for (int ii = 0; ii < 16; ii++) cp_piece(mB, nB, chunkK0(i, 1), s1, ii);
        cp_commit();
        cp_wait<1>();
        __syncthreads();
        ldA(sbase, 0, af[0]);
        ldB(sbase, 0, bf[0]);
    }

    int cmB = tileMB(0), cnB = tileNB(0);   // compute-tile bases (for epilogue)

#pragma unroll 1
    for (int gc = 0; gc < gcEnd; gc++) {
        const int cc = gc & 31;
        const uint32_t st  = sbase + (uint32_t)(gc % STAGES) * STAGE_BYTES;
        const uint32_t stn = sbase + (uint32_t)((gc + 1) % STAGES) * STAGE_BYTES;

        // loading coords for chunk gc+2 (may belong to a later tile)
        const bool doLoad = (gc + 2 < gcEnd);
        int lmB = 0, lnB = 0, lk0 = 0;
        uint32_t lst = 0;
        if (doLoad) {
            const int lj = (gc + 2) >> 5;
            lmB = tileMB(lj);
            lnB = tileNB(lj);
            lk0 = chunkK0((lnB / BN) >> 1, (gc + 2) & 31);
            lst = sbase + (uint32_t)((gc + 2) % STAGES) * STAGE_BYTES;
        }

#pragma unroll
        for (int kstep = 0; kstep < 4; kstep++) {
            const int cur = kstep & 1, nxt = cur ^ 1;
            if (kstep < 3) {
                ldA(st, kstep + 1, af[nxt]);
                ldB(st, kstep + 1, bf[nxt]);
                if (doLoad && kstep < 2) {
#pragma unroll
                    for (int ii = 0; ii < 8; ii++) cp_piece(lmB, lnB, lk0, lst, kstep * 8 + ii);
                    if (kstep == 1) cp_commit();
                }
            } else {
                // boundary: publish stage gc+1 BEFORE reading it (race-free)
                cp_wait<1>();
                __syncthreads();
                if (gc + 1 < gcEnd) {
                    ldA(stn, 0, af[nxt]);
                    ldB(stn, 0, bf[nxt]);
                }
            }
#pragma unroll
            for (int nip = 0; nip < 4; nip++)
#pragma unroll
                for (int half = 0; half < 2; half++) {
                    const int ni = nip * 2 + half;
#pragma unroll
                    for (int mi = 0; mi < 4; mi++)
                        mma_f16(acc[mi][ni], af[cur][mi], &bf[cur][nip * 4 + half * 2]);
                }
        }

        // tile finished: epilogue (overlaps the in-flight cp.async for gc+2)
        if (cc == 31) {
            const int qid = lane >> 2;
            const int qn = (lane & 3) * 2;
#pragma unroll
            for (int mi = 0; mi < 4; mi++) {
                const int m0 = cmB + wm * 64 + mi * 16 + qid;
#pragma unroll
                for (int ni = 0; ni < 8; ni++) {
                    const int ncol = wn * 64 + ni * 8 + qn;
                    const float2 bv = __ldg(reinterpret_cast<const float2*>(&bias[cnB + ncol]));
                    float2 o0 = make_float2(acc[mi][ni][0] + bv.x, acc[mi][ni][1] + bv.y);
                    float2 o1 = make_float2(acc[mi][ni][2] + bv.x, acc[mi][ni][3] + bv.y);
                    *reinterpret_cast<float2*>(&out[(size_t)m0 * N_DIM + cnB + ncol]) = o0;
                    *reinterpret_cast<float2*>(&out[(size_t)(m0 + 8) * N_DIM + cnB + ncol]) = o1;
                    acc[mi][ni][0] = 0.0f; acc[mi][ni][1] = 0.0f;
                    acc[mi][ni][2] = 0.0f; acc[mi][ni][3] = 0.0f;
                }
            }
            if (gc + 1 < gcEnd) {
                const int nj = (gc + 1) >> 5;
                cmB = tileMB(nj);
                cnB = tileNB(nj);
            }
        }
    }
}

// ---------- launch ----------
extern "C" void kernel_launch(void* const* d_in, const int* in_sizes, int n_in,
                              void* d_out, int out_size) {
    const float* x    = (const float*)d_in[0];
    const float* w    = (const float*)d_in[1];
    const float* bias = (const float*)d_in[2];
    float* out = (float*)d_out;

    cvt_kernel<<<6144, 256>>>(x, w);

    cudaFuncSetAttribute(bs_f16_kernel, cudaFuncAttributeMaxDynamicSharedMemorySize, SMEM_DYN);
    bs_f16_kernel<<<GRID_P, 128, SMEM_DYN>>>(bias, out);
}

// round 14
// speedup vs baseline: 1.0609x; 1.0060x over previous
#include <cuda_runtime.h>
#include <cuda_fp16.h>
#include <cstdint>

// BlockSparse: out = x @ (mask*W)^T + bias.  M=8192, N=4096, K=4096 fp32.
// Mask: 256-blocks, keep (i,j) iff (i+j)%16 >= 8 -> K_eff = 2048 per column block.
//
// R14: R13 persistent structure (fp16 m16n8k16, warp 64x64, CTA 128x128,
// 3-stage cp.async, 2 CTAs/SM, race-free boundary) plus:
//  - STAGGER: second resident CTA group (bid>=152) delays ~384cyc at start so
//    the two co-resident CTAs' chunk-boundary stalls interleave instead of
//    phase-locking (R12/R13 both plateaued at tensor=76%).
//  - cvt prepass uses 16B stores (8 floats/iter).

#define M_DIM 8192
#define N_DIM 4096
#define K_DIM 4096

#define BM 128
#define BN 128
#define BK 64
#define NTILES 2048                        // 64 m-tiles x 32 n-tiles
#define GRID_P 304                         // 2 CTAs/SM x 152 SMs
#define STAGES 3
#define A_PART (128 * 128)                 // 16 KB
#define B_PART (128 * 128)                 // 16 KB
#define OFF_A 0
#define OFF_B (A_PART)
#define STAGE_BYTES (A_PART + B_PART)      // 32 KB
#define SMEM_DYN (STAGES * STAGE_BYTES + 256)

__device__ __half g_x[(size_t)M_DIM * K_DIM];
__device__ __half g_w[(size_t)N_DIM * K_DIM];

// ---------- helpers ----------
__device__ __forceinline__ uint32_t smem_u32(const void* p) {
    uint32_t a;
    asm("{ .reg .u64 t; cvta.to.shared.u64 t, %1; cvt.u32.u64 %0, t; }" : "=r"(a) : "l"(p));
    return a;
}
__device__ __forceinline__ void cp16(uint32_t dst, const void* src) {
    asm volatile("cp.async.cg.shared.global [%0], [%1], 16;" :: "r"(dst), "l"(src));
}
__device__ __forceinline__ void cp_commit() { asm volatile("cp.async.commit_group;" ::: "memory"); }
template <int N> __device__ __forceinline__ void cp_wait() {
    asm volatile("cp.async.wait_group %0;" :: "n"(N) : "memory");
}
__device__ __forceinline__ void ldsm_x4(uint32_t* r, uint32_t addr) {
    asm volatile("ldmatrix.sync.aligned.m8n8.x4.shared.b16 {%0,%1,%2,%3}, [%4];"
                 : "=r"(r[0]), "=r"(r[1]), "=r"(r[2]), "=r"(r[3]) : "r"(addr));
}
__device__ __forceinline__ void mma_f16(float* c, const uint32_t* a, const uint32_t* b) {
    asm volatile(
        "mma.sync.aligned.m16n8k16.row.col.f32.f16.f16.f32 "
        "{%0,%1,%2,%3}, {%4,%5,%6,%7}, {%8,%9}, {%0,%1,%2,%3};"
        : "+f"(c[0]), "+f"(c[1]), "+f"(c[2]), "+f"(c[3])
        : "r"(a[0]), "r"(a[1]), "r"(a[2]), "r"(a[3]), "r"(b[0]), "r"(b[1]));
}
__device__ __forceinline__ uint32_t swz(int r, int c) {
    return (uint32_t)(r * 128 + ((c ^ (r & 7)) << 4));
}

// ---------- prepass: fp32 -> fp16 (16B stores); W converts only kept blocks ----------
__global__ __launch_bounds__(256) void cvt_kernel(const float* __restrict__ x,
                                                  const float* __restrict__ w) {
    const long NX8 = (long)M_DIM * K_DIM / 8;     // x: groups of 8 floats
    const long NW8 = (long)N_DIM * 8 * 32;        // kept w: 8 blocks x 256 floats / 8
    const long NT = NX8 + NW8;
    long stride = (long)gridDim.x * blockDim.x;
    for (long t = (long)blockIdx.x * blockDim.x + threadIdx.x; t < NT; t += stride) {
        long o8;
        const float* src;
        __half* dst;
        if (t < NX8) {
            o8 = t;
            src = x;
            dst = g_x;
        } else {
            const long u = t - NX8;
            const int row = (int)(u >> 8);            // 256 groups per row
            const int rem = (int)(u & 255);
            const int kb = rem >> 5;                  // kept-block 0..7
            const int f8 = rem & 31;
            const int i = row >> 8;                   // n-block index
            const int j = (8 + kb - (i & 15)) & 15;   // kept k-block
            o8 = (long)row * (K_DIM / 8) + j * 32 + f8;
            src = w;
            dst = g_w;
        }
        float4 v0 = reinterpret_cast<const float4*>(src)[2 * o8];
        float4 v1 = reinterpret_cast<const float4*>(src)[2 * o8 + 1];
        __half2 h0 = __floats2half2_rn(v0.x, v0.y);
        __half2 h1 = __floats2half2_rn(v0.z, v0.w);
        __half2 h2 = __floats2half2_rn(v1.x, v1.y);
        __half2 h3 = __floats2half2_rn(v1.z, v1.w);
        uint4 pk;
        pk.x = *reinterpret_cast<uint32_t*>(&h0);
        pk.y = *reinterpret_cast<uint32_t*>(&h1);
        pk.z = *reinterpret_cast<uint32_t*>(&h2);
        pk.w = *reinterpret_cast<uint32_t*>(&h3);
        reinterpret_cast<uint4*>(dst)[o8] = pk;
    }
}

// ---------- main GEMM (persistent, staggered) ----------
__global__ __launch_bounds__(128, 2)
void bs_f16_kernel(const float* __restrict__ bias, float* __restrict__ out) {
    extern __shared__ char smem[];
    const uint32_t sbase = smem_u32(smem);

    const int tid = threadIdx.x;
    const int wid = tid >> 5;
    const int lane = tid & 31;
    const int wm = wid & 1;
    const int wn = wid >> 1;
    const int t0 = blockIdx.x;

    // stagger: second resident group delays ~half a chunk so co-resident
    // CTAs' boundary stalls interleave.
    if (t0 >= 152) {
        long long s = clock64();
        while (clock64() - s < 384) { }
    }

    int nT = 0;
    for (int t = t0; t < NTILES; t += GRID_P) nT++;
    const int gcEnd = nT * 32;
    if (gcEnd == 0) return;

    auto tileMB = [&](int j) { return ((t0 + GRID_P * j) >> 5) * BM; };
    auto tileNB = [&](int j) { return ((t0 + GRID_P * j) & 31) * BN; };
    auto chunkK0 = [&](int i, int cc) {
        const int kb = cc >> 2;
        const int j = (8 + kb - (i & 15)) & 15;
        return j * 256 + (cc & 3) * BK;
    };

    auto cp_piece = [&](int lmB, int lnB, int lk0, uint32_t st, int ii) {
        const int idx = tid + ii * 128;
        uint32_t dst;
        const __half* src;
        if (idx < 1024) {
            const int r = idx >> 3, cc = idx & 7;
            src = g_x + ((size_t)(lmB + r) * K_DIM + lk0 + cc * 8);
            dst = st + OFF_A + swz(r, cc);
        } else {
            const int t = idx - 1024;
            const int r = t >> 3, cc = t & 7;
            src = g_w + ((size_t)(lnB + r) * K_DIM + lk0 + cc * 8);
            dst = st + OFF_B + swz(r, cc);
        }
        cp16(dst, src);
    };

    const int q = lane >> 3;
    const int l7 = lane & 7;
    const int qa = q >> 1;
    const int qb = q & 1;
    const uint32_t aOff0 = OFF_A + (uint32_t)(wm * 64 + ((q & 1) << 3) + l7) * 128;
    const uint32_t bOff0 = OFF_B + (uint32_t)(wn * 64 + ((q >> 1) << 3) + l7) * 128;

    auto ldA = [&](uint32_t stb, int kk, uint32_t (*dst)[4]) {
        const uint32_t t = (uint32_t)(((2 * kk + qa) ^ l7) << 4);
#pragma unroll
        for (int mi = 0; mi < 4; mi++)
            ldsm_x4(dst[mi], stb + aOff0 + (uint32_t)(mi * 16 * 128) + t);
    };
    auto ldB = [&](uint32_t stb, int kk, uint32_t* dst) {
        const uint32_t t = (uint32_t)(((2 * kk + qb) ^ l7) << 4);
#pragma unroll
        for (int nip = 0; nip < 4; nip++)
            ldsm_x4(dst + nip * 4, stb + bOff0 + (uint32_t)(nip * 16 * 128) + t);
    };

    float acc[4][8][4];
#pragma unroll
    for (int a = 0; a < 4; a++)
#pragma unroll
        for (int b = 0; b < 8; b++)
#pragma unroll
            for (int p = 0; p < 4; p++) acc[a][b][p] = 0.0f;

    uint32_t af[2][4][4];
    uint32_t bf[2][16];

    // prologue: chunks 0 and 1 of tile 0
    {
        const int mB = tileMB(0), nB = tileNB(0), i = (tileNB(0) / BN) >> 1;
#pragma unroll
        for (int ii = 0; ii < 16; ii++) cp_piece(mB, nB, chunkK0(i, 0), sbase, ii);
        cp_commit();
        const uint32_t s1 = sbase + STAGE_BYTES;
#pragma unroll
        for (int ii = 0; ii < 16; ii++) cp_piece(mB, nB, chunkK0(i, 1), s1, ii);
        cp_commit();
        cp_wait<1>();
        __syncthreads();
        ldA(sbase, 0, af[0]);
        ldB(sbase, 0, bf[0]);
    }

    int cmB = tileMB(0), cnB = tileNB(0);

#pragma unroll 1
    for (int gc = 0; gc < gcEnd; gc++) {
        const int cc = gc & 31;
        const uint32_t st  = sbase + (uint32_t)(gc % STAGES) * STAGE_BYTES;
        const uint32_t stn = sbase + (uint32_t)((gc + 1) % STAGES) * STAGE_BYTES;

        const bool doLoad = (gc + 2 < gcEnd);
        int lmB = 0, lnB = 0, lk0 = 0;
        uint32_t lst = 0;
        if (doLoad) {
            const int lj = (gc + 2) >> 5;
            lmB = tileMB(lj);
            lnB = tileNB(lj);
            lk0 = chunkK0((lnB / BN) >> 1, (gc + 2) & 31);
            lst = sbase + (uint32_t)((gc + 2) % STAGES) * STAGE_BYTES;
        }

#pragma unroll
        for (int kstep = 0; kstep < 4; kstep++) {
            const int cur = kstep & 1, nxt = cur ^ 1;
            if (kstep < 3) {
                ldA(st, kstep + 1, af[nxt]);
                ldB(st, kstep + 1, bf[nxt]);
                if (doLoad && kstep < 2) {
#pragma unroll
                    for (int ii = 0; ii < 8; ii++) cp_piece(lmB, lnB, lk0, lst, kstep * 8 + ii);
                    if (kstep == 1) cp_commit();
                }
            } else {
                cp_wait<1>();
                __syncthreads();
                if (gc + 1 < gcEnd) {
                    ldA(stn, 0, af[nxt]);
                    ldB(stn, 0, bf[nxt]);
                }
            }
#pragma unroll
            for (int nip = 0; nip < 4; nip++)
#pragma unroll
                for (int half = 0; half < 2; half++) {
                    const int ni = nip * 2 + half;
#pragma unroll
                    for (int mi = 0; mi < 4; mi++)
                        mma_f16(acc[mi][ni], af[cur][mi], &bf[cur][nip * 4 + half * 2]);
                }
        }

        if (cc == 31) {
            const int qid = lane >> 2;
            const int qn = (lane & 3) * 2;
#pragma unroll
            for (int mi = 0; mi < 4; mi++) {
                const int m0 = cmB + wm * 64 + mi * 16 + qid;
#pragma unroll
                for (int ni = 0; ni < 8; ni++) {
                    const int ncol = wn * 64 + ni * 8 + qn;
                    const float2 bv = __ldg(reinterpret_cast<const float2*>(&bias[cnB + ncol]));
                    float2 o0 = make_float2(acc[mi][ni][0] + bv.x, acc[mi][ni][1] + bv.y);
                    float2 o1 = make_float2(acc[mi][ni][2] + bv.x, acc[mi][ni][3] + bv.y);
                    *reinterpret_cast<float2*>(&out[(size_t)m0 * N_DIM + cnB + ncol]) = o0;
                    *reinterpret_cast<float2*>(&out[(size_t)(m0 + 8) * N_DIM + cnB + ncol]) = o1;
                    acc[mi][ni][0] = 0.0f; acc[mi][ni][1] = 0.0f;
                    acc[mi][ni][2] = 0.0f; acc[mi][ni][3] = 0.0f;
                }
            }
            if (gc + 1 < gcEnd) {
                const int nj = (gc + 1) >> 5;
                cmB = tileMB(nj);
                cnB = tileNB(nj);
            }
        }
    }
}

// ---------- launch ----------
extern "C" void kernel_launch(void* const* d_in, const int* in_sizes, int n_in,
                              void* d_out, int out_size) {
    const float* x    = (const float*)d_in[0];
    const float* w    = (const float*)d_in[1];
    const float* bias = (const float*)d_in[2];
    float* out = (float*)d_out;

    cvt_kernel<<<6144, 256>>>(x, w);

    cudaFuncSetAttribute(bs_f16_kernel, cudaFuncAttributeMaxDynamicSharedMemorySize, SMEM_DYN);
    bs_f16_kernel<<<GRID_P, 128, SMEM_DYN>>>(bias, out);
}

// round 15
// speedup vs baseline: 1.0916x; 1.0290x over previous
#include <cuda_runtime.h>
#include <cuda_fp16.h>
#include <cstdint>

// BlockSparse: out = x @ (mask*W)^T + bias.  M=8192, N=4096, K=4096 fp32.
// Mask: 256-blocks, keep (i,j) iff (i+j)%16 >= 8 -> K_eff = 2048 per column block.
//
// R15: fp16 m16n8k16, warp 64x64, CTA 128x128, 3-stage cp.async, 2 CTAs/SM,
// persistent 304 CTAs.  KEY CHANGE: all asm-volatile ops execute in source
// order, so the old [8 LDSM][8 cp][32 MMA] bursts starved the tensor pipe.
// Now interleaved per nip-group: 1 LDSM, 4 MMA, 1 LDSM, 4 MMA, 2 cp.async.

#define M_DIM 8192
#define N_DIM 4096
#define K_DIM 4096

#define BM 128
#define BN 128
#define BK 64
#define NTILES 2048
#define GRID_P 304
#define STAGES 3
#define A_PART (128 * 128)
#define B_PART (128 * 128)
#define OFF_A 0
#define OFF_B (A_PART)
#define STAGE_BYTES (A_PART + B_PART)      // 32 KB
#define SMEM_DYN (STAGES * STAGE_BYTES + 256)

__device__ __half g_x[(size_t)M_DIM * K_DIM];
__device__ __half g_w[(size_t)N_DIM * K_DIM];

// ---------- helpers ----------
__device__ __forceinline__ uint32_t smem_u32(const void* p) {
    uint32_t a;
    asm("{ .reg .u64 t; cvta.to.shared.u64 t, %1; cvt.u32.u64 %0, t; }" : "=r"(a) : "l"(p));
    return a;
}
__device__ __forceinline__ void cp16(uint32_t dst, const void* src) {
    asm volatile("cp.async.cg.shared.global [%0], [%1], 16;" :: "r"(dst), "l"(src));
}
__device__ __forceinline__ void cp_commit() { asm volatile("cp.async.commit_group;" ::: "memory"); }
template <int N> __device__ __forceinline__ void cp_wait() {
    asm volatile("cp.async.wait_group %0;" :: "n"(N) : "memory");
}
__device__ __forceinline__ void ldsm_x4(uint32_t* r, uint32_t addr) {
    asm volatile("ldmatrix.sync.aligned.m8n8.x4.shared.b16 {%0,%1,%2,%3}, [%4];"
                 : "=r"(r[0]), "=r"(r[1]), "=r"(r[2]), "=r"(r[3]) : "r"(addr));
}
__device__ __forceinline__ void mma_f16(float* c, const uint32_t* a, const uint32_t* b) {
    asm volatile(
        "mma.sync.aligned.m16n8k16.row.col.f32.f16.f16.f32 "
        "{%0,%1,%2,%3}, {%4,%5,%6,%7}, {%8,%9}, {%0,%1,%2,%3};"
        : "+f"(c[0]), "+f"(c[1]), "+f"(c[2]), "+f"(c[3])
        : "r"(a[0]), "r"(a[1]), "r"(a[2]), "r"(a[3]), "r"(b[0]), "r"(b[1]));
}
__device__ __forceinline__ uint32_t swz(int r, int c) {
    return (uint32_t)(r * 128 + ((c ^ (r & 7)) << 4));
}

// ---------- prepass: fp32 -> fp16 (16B stores); W converts only kept blocks ----------
__global__ __launch_bounds__(256) void cvt_kernel(const float* __restrict__ x,
                                                  const float* __restrict__ w) {
    const long NX8 = (long)M_DIM * K_DIM / 8;
    const long NW8 = (long)N_DIM * 8 * 32;
    const long NT = NX8 + NW8;
    long stride = (long)gridDim.x * blockDim.x;
    for (long t = (long)blockIdx.x * blockDim.x + threadIdx.x; t < NT; t += stride) {
        long o8;
        const float* src;
        __half* dst;
        if (t < NX8) {
            o8 = t;
            src = x;
            dst = g_x;
        } else {
            const long u = t - NX8;
            const int row = (int)(u >> 8);
            const int rem = (int)(u & 255);
            const int kb = rem >> 5;
            const int f8 = rem & 31;
            const int i = row >> 8;
            const int j = (8 + kb - (i & 15)) & 15;
            o8 = (long)row * (K_DIM / 8) + j * 32 + f8;
            src = w;
            dst = g_w;
        }
        float4 v0 = reinterpret_cast<const float4*>(src)[2 * o8];
        float4 v1 = reinterpret_cast<const float4*>(src)[2 * o8 + 1];
        __half2 h0 = __floats2half2_rn(v0.x, v0.y);
        __half2 h1 = __floats2half2_rn(v0.z, v0.w);
        __half2 h2 = __floats2half2_rn(v1.x, v1.y);
        __half2 h3 = __floats2half2_rn(v1.z, v1.w);
        uint4 pk;
        pk.x = *reinterpret_cast<uint32_t*>(&h0);
        pk.y = *reinterpret_cast<uint32_t*>(&h1);
        pk.z = *reinterpret_cast<uint32_t*>(&h2);
        pk.w = *reinterpret_cast<uint32_t*>(&h3);
        reinterpret_cast<uint4*>(dst)[o8] = pk;
    }
}

// ---------- main GEMM (persistent, interleaved issue) ----------
__global__ __launch_bounds__(128, 2)
void bs_f16_kernel(const float* __restrict__ bias, float* __restrict__ out) {
    extern __shared__ char smem[];
    const uint32_t sbase = smem_u32(smem);

    const int tid = threadIdx.x;
    const int wid = tid >> 5;
    const int lane = tid & 31;
    const int wm = wid & 1;
    const int wn = wid >> 1;
    const int t0 = blockIdx.x;

    int nT = 0;
    for (int t = t0; t < NTILES; t += GRID_P) nT++;
    const int gcEnd = nT * 32;
    if (gcEnd == 0) return;

    auto tileMB = [&](int j) { return ((t0 + GRID_P * j) >> 5) * BM; };
    auto tileNB = [&](int j) { return ((t0 + GRID_P * j) & 31) * BN; };
    auto chunkK0 = [&](int i, int cc) {
        const int kb = cc >> 2;
        const int j = (8 + kb - (i & 15)) & 15;
        return j * 256 + (cc & 3) * BK;
    };

    auto cp_piece = [&](int lmB, int lnB, int lk0, uint32_t st, int ii) {
        const int idx = tid + ii * 128;
        uint32_t dst;
        const __half* src;
        if (idx < 1024) {
            const int r = idx >> 3, cc = idx & 7;
            src = g_x + ((size_t)(lmB + r) * K_DIM + lk0 + cc * 8);
            dst = st + OFF_A + swz(r, cc);
        } else {
            const int t = idx - 1024;
            const int r = t >> 3, cc = t & 7;
            src = g_w + ((size_t)(lnB + r) * K_DIM + lk0 + cc * 8);
            dst = st + OFF_B + swz(r, cc);
        }
        cp16(dst, src);
    };

    const int q = lane >> 3;
    const int l7 = lane & 7;
    const int qa = q >> 1;
    const int qb = q & 1;
    const uint32_t aOff0 = OFF_A + (uint32_t)(wm * 64 + ((q & 1) << 3) + l7) * 128;
    const uint32_t bOff0 = OFF_B + (uint32_t)(wn * 64 + ((q >> 1) << 3) + l7) * 128;

    float acc[4][8][4];
#pragma unroll
    for (int a = 0; a < 4; a++)
#pragma unroll
        for (int b = 0; b < 8; b++)
#pragma unroll
            for (int p = 0; p < 4; p++) acc[a][b][p] = 0.0f;

    uint32_t af[2][4][4];
    uint32_t bf[2][16];

    // prologue: chunks 0 and 1 of tile 0; fragments for kstep 0
    {
        const int mB = tileMB(0), nB = tileNB(0), i = (tileNB(0) / BN) >> 1;
#pragma unroll
        for (int ii = 0; ii < 16; ii++) cp_piece(mB, nB, chunkK0(i, 0), sbase, ii);
        cp_commit();
        const uint32_t s1 = sbase + STAGE_BYTES;
#pragma unroll
        for (int ii = 0; ii < 16; ii++) cp_piece(mB, nB, chunkK0(i, 1), s1, ii);
        cp_commit();
        cp_wait<1>();
        __syncthreads();
        const uint32_t tA = (uint32_t)((qa ^ l7) << 4);
        const uint32_t tB = (uint32_t)((qb ^ l7) << 4);
#pragma unroll
        for (int mi = 0; mi < 4; mi++)
            ldsm_x4(af[0][mi], sbase + aOff0 + (uint32_t)(mi * 2048) + tA);
#pragma unroll
        for (int nip = 0; nip < 4; nip++)
            ldsm_x4(&bf[0][nip * 4], sbase + bOff0 + (uint32_t)(nip * 2048) + tB);
    }

    int cmB = tileMB(0), cnB = tileNB(0);

#pragma unroll 1
    for (int gc = 0; gc < gcEnd; gc++) {
        const int cc = gc & 31;
        const uint32_t st  = sbase + (uint32_t)(gc % STAGES) * STAGE_BYTES;
        const uint32_t stn = sbase + (uint32_t)((gc + 1) % STAGES) * STAGE_BYTES;

        const bool doLoad = (gc + 2 < gcEnd);
        int lmB = 0, lnB = 0, lk0 = 0;
        uint32_t lst = 0;
        if (doLoad) {
            const int lj = (gc + 2) >> 5;
            lmB = tileMB(lj);
            lnB = tileNB(lj);
            lk0 = chunkK0((lnB / BN) >> 1, (gc + 2) & 31);
            lst = sbase + (uint32_t)((gc + 2) % STAGES) * STAGE_BYTES;
        }

#pragma unroll
        for (int kstep = 0; kstep < 4; kstep++) {
            const int cur = kstep & 1, nxt = cur ^ 1;

            uint32_t ldb;       // stage to prefetch fragments from
            int lkk;            // kstep (within that stage) to prefetch
            bool doFrag;
            if (kstep < 3) {
                ldb = st; lkk = kstep + 1; doFrag = true;
            } else {
                // boundary: publish stage gc+1 BEFORE reading it
                cp_wait<1>();
                __syncthreads();
                ldb = stn; lkk = 0; doFrag = (gc + 1 < gcEnd);
            }
            const uint32_t aBase = ldb + aOff0 + (uint32_t)(((2 * lkk + qa) ^ l7) << 4);
            const uint32_t bBase = ldb + bOff0 + (uint32_t)(((2 * lkk + qb) ^ l7) << 4);
            const bool doCp = doLoad && (kstep < 2);

            // interleaved issue: per nip group -> 1 LDSM, 4 MMA, 1 LDSM, 4 MMA, 2 cp
#pragma unroll
            for (int nip = 0; nip < 4; nip++) {
                if (doFrag) ldsm_x4(af[nxt][nip], aBase + (uint32_t)(nip * 2048));
#pragma unroll
                for (int mi = 0; mi < 4; mi++)
                    mma_f16(acc[mi][2 * nip], af[cur][mi], &bf[cur][nip * 4]);
                if (doFrag) ldsm_x4(&bf[nxt][nip * 4], bBase + (uint32_t)(nip * 2048));
#pragma unroll
                for (int mi = 0; mi < 4; mi++)
                    mma_f16(acc[mi][2 * nip + 1], af[cur][mi], &bf[cur][nip * 4 + 2]);
                if (doCp) {
                    cp_piece(lmB, lnB, lk0, lst, kstep * 8 + nip * 2);
                    cp_piece(lmB, lnB, lk0, lst, kstep * 8 + nip * 2 + 1);
                }
            }
            if (doCp && kstep == 1) cp_commit();
        }

        // tile finished: epilogue (overlaps in-flight cp.async for gc+2)
        if (cc == 31) {
            const int qid = lane >> 2;
            const int qn = (lane & 3) * 2;
#pragma unroll
            for (int mi = 0; mi < 4; mi++) {
                const int m0 = cmB + wm * 64 + mi * 16 + qid;
#pragma unroll
                for (int ni = 0; ni < 8; ni++) {
                    const int ncol = wn * 64 + ni * 8 + qn;
                    const float2 bv = __ldg(reinterpret_cast<const float2*>(&bias[cnB + ncol]));
                    float2 o0 = make_float2(acc[mi][ni][0] + bv.x, acc[mi][ni][1] + bv.y);
                    float2 o1 = make_float2(acc[mi][ni][2] + bv.x, acc[mi][ni][3] + bv.y);
                    *reinterpret_cast<float2*>(&out[(size_t)m0 * N_DIM + cnB + ncol]) = o0;
                    *reinterpret_cast<float2*>(&out[(size_t)(m0 + 8) * N_DIM + cnB + ncol]) = o1;
                    acc[mi][ni][0] = 0.0f; acc[mi][ni][1] = 0.0f;
                    acc[mi][ni][2] = 0.0f; acc[mi][ni][3] = 0.0f;
                }
            }
            if (gc + 1 < gcEnd) {
                const int nj = (gc + 1) >> 5;
                cmB = tileMB(nj);
                cnB = tileNB(nj);
            }
        }
    }
}

// ---------- launch ----------
extern "C" void kernel_launch(void* const* d_in, const int* in_sizes, int n_in,
                              void* d_out, int out_size) {
    const float* x    = (const float*)d_in[0];
    const float* w    = (const float*)d_in[1];
    const float* bias = (const float*)d_in[2];
    float* out = (float*)d_out;

    cvt_kernel<<<6144, 256>>>(x, w);

    cudaFuncSetAttribute(bs_f16_kernel, cudaFuncAttributeMaxDynamicSharedMemorySize, SMEM_DYN);
    bs_f16_kernel<<<GRID_P, 128, SMEM_DYN>>>(bias, out);
}